// round 4
// baseline (speedup 1.0000x reference)
#include <cuda_runtime.h>

#define HID  128
#define NH   8
#define NSEQ 4096
#define BP   4
#define SROW 4097   // h has 4097 rows per batch; last row is hg

__device__ float g_u[BP*NH*HID];
__device__ float g_s[BP*NH*NSEQ];
__device__ float g_w[BP*NH*HID];
__device__ float g_mh[BP*HID];
__device__ float g_a[BP*NSEQ];
__device__ float g_bv[BP*NSEQ];

__device__ __forceinline__ float wsum(float v) {
    #pragma unroll
    for (int o = 16; o; o >>= 1) v += __shfl_xor_sync(0xffffffffu, v, o);
    return v;
}

// ---------------- A: q = hg @ W_q ; u_h = W_k_head @ q_h ----------------
__global__ void kA(const float* __restrict__ h, const float* __restrict__ Wq,
                   const float* __restrict__ Wkv) {
    int b = blockIdx.x, tid = threadIdx.x;
    int t = tid & 127, k = tid >> 7;
    __shared__ float hg[HID], qp[4][HID], qs[HID];
    if (tid < HID) hg[tid] = h[((size_t)b*SROW + NSEQ)*HID + tid];
    __syncthreads();
    float q = 0.f;
    #pragma unroll
    for (int d = k*32; d < k*32 + 32; d++) q += hg[d]*Wq[d*HID + t];
    qp[k][t] = q;
    __syncthreads();
    if (tid < HID) qs[tid] = qp[0][tid] + qp[1][tid] + qp[2][tid] + qp[3][tid];
    __syncthreads();
    #pragma unroll
    for (int it = 0; it < 2; it++) {
        int idx = tid + it*512;
        int hh = idx >> 7, tt = idx & 127;
        float u = 0.f;
        #pragma unroll
        for (int d = 0; d < 16; d++) u += Wkv[tt*256 + hh*16 + d]*qs[hh*16 + d];
        g_u[(b*NH + hh)*HID + tt] = u;
    }
}

// ---------------- B: s[b,h,n] = 0.25 * (hn[n] . u[b,h]) ----------------
// 256 thr = 8 warps; each warp does 4 rows (MLP=4). grid (NSEQ/32, BP).
__global__ void kB(const float* __restrict__ h) {
    int b = blockIdx.y, tid = threadIdx.x;
    int warp = tid >> 5, lane = tid & 31;
    __shared__ float4 us4[NH][32];
    ((float4*)us4)[tid] = ((const float4*)&g_u[b*NH*HID])[tid];
    __syncthreads();
    int row0 = blockIdx.x*32 + warp*4;
    const float* base = &h[((size_t)b*SROW + row0)*HID];
    float4 r[4];
    #pragma unroll
    for (int i = 0; i < 4; i++)
        r[i] = *(const float4*)&base[(size_t)i*HID + lane*4];
    float out = 0.f;
    #pragma unroll
    for (int hh = 0; hh < NH; hh++) {
        float4 u4 = us4[hh][lane];
        #pragma unroll
        for (int i = 0; i < 4; i++) {
            float d = r[i].x*u4.x + r[i].y*u4.y + r[i].z*u4.z + r[i].w*u4.w;
            d = wsum(d);
            if (lane == hh*4 + i) out = d;
        }
    }
    g_s[(b*NH + (lane >> 2))*NSEQ + row0 + (lane & 3)] = out*0.25f;
}

// ---- C1: per (b,h): softmax-normalize scores in place; zero g_w ----
__global__ void kC1() {
    int hh = blockIdx.x, b = blockIdx.y, t = threadIdx.x;   // 512 threads
    __shared__ float red[512];
    float4* srow = (float4*)&g_s[(b*NH + hh)*NSEQ];
    float4 v[2];
    v[0] = srow[t]; v[1] = srow[t + 512];
    float mx = fmaxf(fmaxf(fmaxf(v[0].x, v[0].y), fmaxf(v[0].z, v[0].w)),
                     fmaxf(fmaxf(v[1].x, v[1].y), fmaxf(v[1].z, v[1].w)));
    red[t] = mx; __syncthreads();
    for (int o = 256; o; o >>= 1) { if (t < o) red[t] = fmaxf(red[t], red[t+o]); __syncthreads(); }
    mx = red[0]; __syncthreads();
    float sm = 0.f;
    #pragma unroll
    for (int i = 0; i < 2; i++) {
        v[i].x = expf(v[i].x - mx); v[i].y = expf(v[i].y - mx);
        v[i].z = expf(v[i].z - mx); v[i].w = expf(v[i].w - mx);
        sm += (v[i].x + v[i].y) + (v[i].z + v[i].w);
    }
    red[t] = sm; __syncthreads();
    for (int o = 256; o; o >>= 1) { if (t < o) red[t] += red[t+o]; __syncthreads(); }
    float inv = 1.f/red[0];
    #pragma unroll
    for (int i = 0; i < 2; i++) {
        v[i].x *= inv; v[i].y *= inv; v[i].z *= inv; v[i].w *= inv;
    }
    srow[t] = v[0]; srow[t + 512] = v[1];
    if (t < HID) g_w[(b*NH + hh)*HID + t] = 0.f;
}

// ---- C2: w[b,h,:] += sum_n p[b,h,n]*hn[n,:]  (512 blocks, MLP=4) ----
#define CHUNK 32
__global__ void kC2(const float* __restrict__ h) {
    int b = blockIdx.y, c = blockIdx.x, tid = threadIdx.x;  // 256 threads
    int lane = tid & 31, slice = tid >> 5;                  // 8 slices x 4 tokens
    __shared__ float ps[NH][CHUNK];
    {   // NH*CHUNK = 256 elements, one per thread
        int hh = tid >> 5, n = tid & 31;
        ps[hh][n] = g_s[(b*NH + hh)*NSEQ + c*CHUNK + n];
    }
    __syncthreads();
    const float* hb = &h[((size_t)b*SROW + c*CHUNK + slice*4)*HID];
    float4 acc[NH];
    #pragma unroll
    for (int hh = 0; hh < NH; hh++) acc[hh] = make_float4(0.f,0.f,0.f,0.f);
    #pragma unroll
    for (int n = 0; n < 4; n++) {
        float4 h4 = *(const float4*)&hb[(size_t)n*HID + lane*4];
        #pragma unroll
        for (int hh = 0; hh < NH; hh++) {
            float p = ps[hh][slice*4 + n];
            acc[hh].x += p*h4.x; acc[hh].y += p*h4.y;
            acc[hh].z += p*h4.z; acc[hh].w += p*h4.w;
        }
    }
    __shared__ float4 sm[8][NH][32];                 // 32KB
    #pragma unroll
    for (int hh = 0; hh < NH; hh++) sm[slice][hh][lane] = acc[hh];
    __syncthreads();
    int hh = tid >> 5;
    float4 r = sm[0][hh][lane];
    #pragma unroll
    for (int s = 1; s < 8; s++) {
        float4 v = sm[s][hh][lane];
        r.x += v.x; r.y += v.y; r.z += v.z; r.w += v.w;
    }
    float* dst = &g_w[(b*NH + hh)*HID + lane*4];
    atomicAdd(dst+0, r.x); atomicAdd(dst+1, r.y);
    atomicAdd(dst+2, r.z); atomicAdd(dst+3, r.w);
}

// ------------ D: y = w @ W_v_head ; mh = y @ W_mhc ------------
__global__ void kD(const float* __restrict__ Wkv, const float* __restrict__ Wmhc) {
    int b = blockIdx.x, tid = threadIdx.x;
    int t = tid & 127, k = tid >> 7;
    __shared__ float ws[NH*HID], part[4][HID], ys[HID];
    for (int i = tid; i < NH*HID; i += 512) ws[i] = g_w[b*NH*HID + i];
    __syncthreads();
    int hh = t >> 4;
    float y = 0.f;
    #pragma unroll
    for (int jj = k*32; jj < k*32 + 32; jj++) y += ws[hh*HID + jj]*Wkv[jj*256 + HID + t];
    part[k][t] = y;
    __syncthreads();
    if (tid < HID) ys[tid] = part[0][tid] + part[1][tid] + part[2][tid] + part[3][tid];
    __syncthreads();
    float m = 0.f;
    #pragma unroll
    for (int c = k*32; c < k*32 + 32; c++) m += ys[c]*Wmhc[c*HID + t];
    part[k][t] = m;
    __syncthreads();
    if (tid < HID) g_mh[b*HID + tid] = part[0][tid] + part[1][tid] + part[2][tid] + part[3][tid];
}

// ------------ E: y2[n] = mh . hn[n]; a = y2*w0, bv = y2*w1 ------------
// 256 thr = 8 warps; each warp does 8 rows (MLP=8). grid (NSEQ/64, BP).
__global__ void kE(const float* __restrict__ h, const float* __restrict__ Wlin) {
    int b = blockIdx.y, tid = threadIdx.x;
    int warp = tid >> 5, lane = tid & 31;
    __shared__ float4 ms4[32];
    __shared__ float w01[2];
    if (tid < 32) ms4[tid] = ((const float4*)&g_mh[b*HID])[tid];
    if (tid < 2)  w01[tid] = Wlin[tid];
    __syncthreads();
    int row0 = blockIdx.x*64 + warp*8;
    const float* base = &h[((size_t)b*SROW + row0)*HID];
    float4 m4 = ms4[lane];
    float out = 0.f;
    #pragma unroll
    for (int i = 0; i < 8; i++) {
        float4 r = *(const float4*)&base[(size_t)i*HID + lane*4];
        float d = r.x*m4.x + r.y*m4.y + r.z*m4.z + r.w*m4.w;
        d = wsum(d);
        if (lane == i) out = d;
    }
    if (lane < 8) {
        g_a [b*NSEQ + row0 + lane] = out*w01[0];
        g_bv[b*NSEQ + row0 + lane] = out*w01[1];
    }
}

// ------------ F: out[b, i*N + j] = a[b,j] + bv[b,i]  (268MB stream) ------------
#define ROWS_F 16
__global__ void kF(float* __restrict__ out) {
    int b = blockIdx.y, t = threadIdx.x;                     // 1024 threads
    int i0 = blockIdx.x*ROWS_F;
    float4 a4 = ((const float4*)&g_a[b*NSEQ])[t];
    const float* bv = &g_bv[b*NSEQ];
    float4* ob = (float4*)&out[((size_t)b*NSEQ + i0)*NSEQ];
    #pragma unroll
    for (int r = 0; r < ROWS_F; r++) {
        float bi = bv[i0 + r];
        float4 o4 = make_float4(a4.x+bi, a4.y+bi, a4.z+bi, a4.w+bi);
        __stwt(&ob[(size_t)r*(NSEQ/4) + t], o4);
    }
}

extern "C" void kernel_launch(void* const* d_in, const int* in_sizes, int n_in,
                              void* d_out, int out_size) {
    const float* h    = (const float*)d_in[0];
    const float* Wq   = (const float*)d_in[1];
    const float* Wkv  = (const float*)d_in[2];
    const float* Wmhc = (const float*)d_in[3];
    const float* Wlin = (const float*)d_in[4];
    float* out = (float*)d_out;

    kA <<<BP, 512>>>(h, Wq, Wkv);
    kB <<<dim3(NSEQ/32, BP), 256>>>(h);
    kC1<<<dim3(NH, BP), 512>>>();
    kC2<<<dim3(NSEQ/CHUNK, BP), 256>>>(h);
    kD <<<BP, 512>>>(Wkv, Wmhc);
    kE <<<dim3(NSEQ/64, BP), 256>>>(h, Wlin);
    kF <<<dim3(NSEQ/ROWS_F, BP), 1024>>>(out);
}

// round 5
// speedup vs baseline: 1.1059x; 1.1059x over previous
#include <cuda_runtime.h>

#define HID  128
#define NH   8
#define NSEQ 4096
#define BP   4
#define SROW 4097   // h has 4097 rows per batch; last row is hg

__device__ float g_u[BP*NH*HID];
__device__ float g_w[BP*NH*HID];     // UNNORMALIZED sum of e_n * hn
__device__ float g_sum[BP*NH];       // sum of e_n
__device__ float g_a[BP*NSEQ];
__device__ float g_bv[BP*NSEQ];

__device__ __forceinline__ float wsum(float v) {
    #pragma unroll
    for (int o = 16; o; o >>= 1) v += __shfl_xor_sync(0xffffffffu, v, o);
    return v;
}

// ---------------- A: q = hg@W_q ; u_h = W_k_head@q_h ; zero accumulators ----------------
__global__ void kA(const float* __restrict__ h, const float* __restrict__ Wq,
                   const float* __restrict__ Wkv) {
    int b = blockIdx.x, tid = threadIdx.x;           // 512 threads
    // zero this batch's accumulators (stream order guarantees visibility to kBC)
    g_w[b*NH*HID + tid]       = 0.f;
    g_w[b*NH*HID + 512 + tid] = 0.f;
    if (tid < NH) g_sum[b*NH + tid] = 0.f;

    int t = tid & 127, k = tid >> 7;
    __shared__ float hg[HID], qp[4][HID], qs[HID];
    if (tid < HID) hg[tid] = h[((size_t)b*SROW + NSEQ)*HID + tid];
    __syncthreads();
    float q = 0.f;
    #pragma unroll
    for (int d = k*32; d < k*32 + 32; d++) q += hg[d]*Wq[d*HID + t];
    qp[k][t] = q;
    __syncthreads();
    if (tid < HID) qs[tid] = qp[0][tid] + qp[1][tid] + qp[2][tid] + qp[3][tid];
    __syncthreads();
    #pragma unroll
    for (int it = 0; it < 2; it++) {
        int idx = tid + it*512;
        int hh = idx >> 7, tt = idx & 127;
        float u = 0.f;
        #pragma unroll
        for (int d = 0; d < 16; d++) u += Wkv[tt*256 + hh*16 + d]*qs[hh*16 + d];
        g_u[(b*NH + hh)*HID + tt] = u;
    }
}

// ---- BC fused: scores -> exp (no max-sub; scores bounded) -> accumulate w, esum ----
// 256 thr = 8 warps; each warp handles 4 rows. grid (NSEQ/32, BP).
__global__ void kBC(const float* __restrict__ h) {
    int b = blockIdx.y, tid = threadIdx.x;
    int warp = tid >> 5, lane = tid & 31;
    __shared__ float4 us4[NH][32];
    ((float4*)us4)[tid] = ((const float4*)&g_u[b*NH*HID])[tid];
    __syncthreads();

    int row0 = blockIdx.x*32 + warp*4;
    const float* base = &h[((size_t)b*SROW + row0)*HID];
    float4 r[4];
    #pragma unroll
    for (int i = 0; i < 4; i++)
        r[i] = *(const float4*)&base[(size_t)i*HID + lane*4];

    // 32 dots (8 heads x 4 rows); wsum broadcasts each result to all lanes
    float d[NH][4];
    #pragma unroll
    for (int hh = 0; hh < NH; hh++) {
        float4 u4 = us4[hh][lane];
        #pragma unroll
        for (int i = 0; i < 4; i++) {
            float t = r[i].x*u4.x + r[i].y*u4.y + r[i].z*u4.z + r[i].w*u4.w;
            d[hh][i] = wsum(t);
        }
    }
    // exp + weighted accumulation (each lane owns its 4-column slice)
    float4 acc[NH]; float es[NH];
    #pragma unroll
    for (int hh = 0; hh < NH; hh++) {
        acc[hh] = make_float4(0.f,0.f,0.f,0.f); es[hh] = 0.f;
        #pragma unroll
        for (int i = 0; i < 4; i++) {
            float e = __expf(0.25f*d[hh][i]);
            es[hh] += e;
            acc[hh].x += e*r[i].x; acc[hh].y += e*r[i].y;
            acc[hh].z += e*r[i].z; acc[hh].w += e*r[i].w;
        }
    }
    // block reduce 8 warps, then atomics into g_w / g_sum
    __shared__ float4 smw[8][NH][32];                // 32KB
    __shared__ float  ses[8][NH];
    #pragma unroll
    for (int hh = 0; hh < NH; hh++) smw[warp][hh][lane] = acc[hh];
    if (lane == 0) {
        #pragma unroll
        for (int hh = 0; hh < NH; hh++) ses[warp][hh] = es[hh];
    }
    __syncthreads();
    int hh2 = tid >> 5;
    float4 rs = smw[0][hh2][lane];
    #pragma unroll
    for (int s = 1; s < 8; s++) {
        float4 v = smw[s][hh2][lane];
        rs.x += v.x; rs.y += v.y; rs.z += v.z; rs.w += v.w;
    }
    float* dst = &g_w[(b*NH + hh2)*HID + lane*4];
    atomicAdd(dst+0, rs.x); atomicAdd(dst+1, rs.y);
    atomicAdd(dst+2, rs.z); atomicAdd(dst+3, rs.w);
    if (tid < NH) {
        float s = 0.f;
        #pragma unroll
        for (int w2 = 0; w2 < 8; w2++) s += ses[w2][tid];
        atomicAdd(&g_sum[b*NH + tid], s);
    }
}

// ---- DE fused: normalize w; y = w@W_v; mh = y@W_mhc; y2 = mh.hn; a/bv ----
// 256 thr = 8 warps x 8 rows. grid (NSEQ/64, BP).
__global__ void kDE(const float* __restrict__ h, const float* __restrict__ Wkv,
                    const float* __restrict__ Wmhc, const float* __restrict__ Wlin) {
    int b = blockIdx.y, tid = threadIdx.x;
    int t = tid & 127, k = tid >> 7;                 // k: 0..1
    __shared__ float ws[NH*HID], ys[HID], ms[HID], part[2][HID];
    __shared__ float ssum[NH], w01[2];
    if (tid < NH) ssum[tid] = g_sum[b*NH + tid];
    if (tid < 2)  w01[tid]  = Wlin[tid];
    __syncthreads();
    #pragma unroll
    for (int it = 0; it < 4; it++) {
        int i = tid + it*256;
        ws[i] = g_w[b*NH*HID + i] / ssum[i >> 7];
    }
    __syncthreads();
    int hh = t >> 4;
    float y = 0.f;
    #pragma unroll
    for (int jj = k*64; jj < k*64 + 64; jj++) y += ws[hh*HID + jj]*Wkv[jj*256 + HID + t];
    part[k][t] = y;
    __syncthreads();
    if (tid < HID) ys[tid] = part[0][tid] + part[1][tid];
    __syncthreads();
    float m = 0.f;
    #pragma unroll
    for (int c = k*64; c < k*64 + 64; c++) m += ys[c]*Wmhc[c*HID + t];
    part[k][t] = m;
    __syncthreads();
    if (tid < HID) ms[tid] = part[0][tid] + part[1][tid];
    __syncthreads();

    int warp = tid >> 5, lane = tid & 31;
    float4 m4 = ((float4*)ms)[lane];
    int row0 = blockIdx.x*64 + warp*8;
    const float* base = &h[((size_t)b*SROW + row0)*HID];
    float out = 0.f;
    #pragma unroll
    for (int i = 0; i < 8; i++) {
        float4 r = *(const float4*)&base[(size_t)i*HID + lane*4];
        float d = r.x*m4.x + r.y*m4.y + r.z*m4.z + r.w*m4.w;
        d = wsum(d);
        if (lane == i) out = d;
    }
    if (lane < 8) {
        g_a [b*NSEQ + row0 + lane] = out*w01[0];
        g_bv[b*NSEQ + row0 + lane] = out*w01[1];
    }
}

// ------------ F: out[b, i*N + j] = a[b,j] + bv[b,i]  (268MB stream) ------------
#define ROWS_F 8
__global__ void kF(float* __restrict__ out) {
    int b = blockIdx.y, t = threadIdx.x;                     // 1024 threads
    int i0 = blockIdx.x*ROWS_F;
    float4 a4 = ((const float4*)&g_a[b*NSEQ])[t];
    const float* bv = &g_bv[b*NSEQ];
    float4* ob = (float4*)&out[((size_t)b*NSEQ + i0)*NSEQ];
    #pragma unroll
    for (int r = 0; r < ROWS_F; r++) {
        float bi = bv[i0 + r];
        float4 o4 = make_float4(a4.x+bi, a4.y+bi, a4.z+bi, a4.w+bi);
        __stwt(&ob[(size_t)r*(NSEQ/4) + t], o4);
    }
}

extern "C" void kernel_launch(void* const* d_in, const int* in_sizes, int n_in,
                              void* d_out, int out_size) {
    const float* h    = (const float*)d_in[0];
    const float* Wq   = (const float*)d_in[1];
    const float* Wkv  = (const float*)d_in[2];
    const float* Wmhc = (const float*)d_in[3];
    const float* Wlin = (const float*)d_in[4];
    float* out = (float*)d_out;

    kA  <<<BP, 512>>>(h, Wq, Wkv);
    kBC <<<dim3(NSEQ/32, BP), 256>>>(h);
    kDE <<<dim3(NSEQ/64, BP), 256>>>(h, Wkv, Wmhc, Wlin);
    kF  <<<dim3(NSEQ/ROWS_F, BP), 1024>>>(out);
}